// round 8
// baseline (speedup 1.0000x reference)
#include <cuda_runtime.h>
#include <cuda_bf16.h>
#include <cstdint>
#include <math.h>

// Problem constants
#define BATCH 2
#define SEQ   2048
#define DMODEL 1024
#define NHEAD 16
#define HDIM  64
#define HALF  32
#define MROWS (BATCH * SEQ)   // 4096

// Scratch (static device globals — allocation-free rule)
__device__ float g_q[MROWS * DMODEL];
__device__ float g_k[MROWS * DMODEL];
__device__ float g_v[MROWS * DMODEL];
__device__ float g_attn[MROWS * DMODEL];

__device__ __forceinline__ float tf32r(float x) {
    float r;
    asm("cvt.rna.tf32.f32 %0, %1;" : "=f"(r) : "f"(x));
    return r;
}

__device__ __forceinline__ void mma_tf32(float c[4], uint32_t a0, uint32_t a1,
                                         uint32_t a2, uint32_t a3,
                                         uint32_t b0, uint32_t b1) {
    asm volatile(
        "mma.sync.aligned.m16n8k8.row.col.f32.tf32.tf32.f32 "
        "{%0,%1,%2,%3}, {%4,%5,%6,%7}, {%8,%9}, {%0,%1,%2,%3};"
        : "+f"(c[0]), "+f"(c[1]), "+f"(c[2]), "+f"(c[3])
        : "r"(a0), "r"(a1), "r"(a2), "r"(a3), "r"(b0), "r"(b1));
}

// ---------------------------------------------------------------------------
// tf32 mma.sync GEMM: C = A @ W^T + bias, optional RoPE.
// CTA 128x128, 512 threads / 16 warps (4x4), warp tile 32x32.
// K chunks of 32, double-buffered smem, stride-36 conflict-free layout.
// ---------------------------------------------------------------------------
#define BM 128
#define BN 128
#define KC 32
#define NT (DMODEL / KC)       // 32
#define AST 36                 // floats per smem row
#define TILEF (128 * AST)
#define SMEM_DYN (4 * TILEF * 4)   // 73728 bytes

__global__ void __launch_bounds__(512, 1)
gemm_tf32_kernel(const float* __restrict__ A,
                 const float* __restrict__ W,
                 const float* __restrict__ bias,
                 float* __restrict__ C,
                 const float* __restrict__ cosb,
                 const float* __restrict__ sinb,
                 int applyRope)
{
    extern __shared__ float ds[];
    float* aT[2] = { ds,             ds + TILEF };
    float* bT[2] = { ds + 2 * TILEF, ds + 3 * TILEF };

    const int tid = threadIdx.x;
    const int wid = tid >> 5;          // 0..15
    const int lid = tid & 31;
    const int wm = (wid & 3) * 32;     // warp M offset
    const int wn = (wid >> 2) * 32;    // warp N offset
    const int m0 = blockIdx.y * BM;
    const int n0 = blockIdx.x * BN;

    // staging: 1024 float4-slots per operand tile, 2 per thread
    const int r0_ = tid >> 3;              // slot tid     : row 0..63
    const int r1_ = (tid + 512) >> 3;      // slot tid+512 : row 64..127
    const int c4_ = (tid & 7) * 4;         // col 0..28

    const float* Abase = A + (size_t)m0 * DMODEL;
    const float* Wbase = W + (size_t)n0 * DMODEL;

    float4 ar[2], br[2];

    #define LOADT(kt) do {                                                     \
        ar[0] = *(const float4*)(Abase + (size_t)r0_ * DMODEL + (kt) * KC + c4_); \
        ar[1] = *(const float4*)(Abase + (size_t)r1_ * DMODEL + (kt) * KC + c4_); \
        br[0] = *(const float4*)(Wbase + (size_t)r0_ * DMODEL + (kt) * KC + c4_); \
        br[1] = *(const float4*)(Wbase + (size_t)r1_ * DMODEL + (kt) * KC + c4_); \
    } while (0)

    #define STST(buf) do {                                                     \
        _Pragma("unroll")                                                      \
        for (int _i = 0; _i < 2; _i++) {                                       \
            const int _r = _i ? r1_ : r0_;                                     \
            float4 _a = ar[_i];                                                \
            _a.x = tf32r(_a.x); _a.y = tf32r(_a.y);                            \
            _a.z = tf32r(_a.z); _a.w = tf32r(_a.w);                            \
            *(float4*)(aT[buf] + _r * AST + c4_) = _a;                         \
            float4 _b = br[_i];                                                \
            _b.x = tf32r(_b.x); _b.y = tf32r(_b.y);                            \
            _b.z = tf32r(_b.z); _b.w = tf32r(_b.w);                            \
            *(float4*)(bT[buf] + _r * AST + c4_) = _b;                         \
        }                                                                      \
    } while (0)

    float acc[2][4][4];
    #pragma unroll
    for (int i = 0; i < 2; i++)
        #pragma unroll
        for (int j = 0; j < 4; j++)
            #pragma unroll
            for (int r = 0; r < 4; r++) acc[i][j][r] = 0.f;

    const int lm = lid >> 2;          // 0..7
    const int lk = lid & 3;           // 0..3

    LOADT(0);
    STST(0);
    __syncthreads();
    LOADT(1);

    for (int kt = 0; kt < NT; kt++) {
        const int cur = kt & 1;
        if (kt + 1 < NT) STST(cur ^ 1);
        if (kt + 2 < NT) LOADT(kt + 2);

        const float* sa = aT[cur] + (wm + lm) * AST + lk;
        const float* sb = bT[cur] + (wn + lm) * AST + lk;
        #pragma unroll
        for (int ks = 0; ks < 4; ks++) {
            uint32_t af[2][4], bf[4][2];
            #pragma unroll
            for (int mf = 0; mf < 2; mf++) {
                af[mf][0] = __float_as_uint(sa[(mf * 16    ) * AST + ks * 8    ]);
                af[mf][1] = __float_as_uint(sa[(mf * 16 + 8) * AST + ks * 8    ]);
                af[mf][2] = __float_as_uint(sa[(mf * 16    ) * AST + ks * 8 + 4]);
                af[mf][3] = __float_as_uint(sa[(mf * 16 + 8) * AST + ks * 8 + 4]);
            }
            #pragma unroll
            for (int nf = 0; nf < 4; nf++) {
                bf[nf][0] = __float_as_uint(sb[(nf * 8) * AST + ks * 8    ]);
                bf[nf][1] = __float_as_uint(sb[(nf * 8) * AST + ks * 8 + 4]);
            }
            #pragma unroll
            for (int mf = 0; mf < 2; mf++)
                #pragma unroll
                for (int nf = 0; nf < 4; nf++)
                    mma_tf32(acc[mf][nf], af[mf][0], af[mf][1], af[mf][2], af[mf][3],
                             bf[nf][0], bf[nf][1]);
        }
        __syncthreads();
    }

    // epilogue: bias (+ RoPE), direct STG
    const int ln = (lid & 3) * 2;
    #pragma unroll
    for (int mf = 0; mf < 2; mf++) {
        #pragma unroll
        for (int half = 0; half < 2; half++) {
            const int m = m0 + wm + mf * 16 + lm + half * 8;
            const int spos = m & (SEQ - 1);
            float* crow = C + (size_t)m * DMODEL;
            #pragma unroll
            for (int nf = 0; nf < 4; nf++) {
                const int n = n0 + wn + nf * 8 + ln;
                float v0 = acc[mf][nf][half * 2 + 0] + bias[n];
                float v1 = acc[mf][nf][half * 2 + 1] + bias[n + 1];
                if (applyRope) {
                    const int fi = (n & (HDIM - 1)) >> 1;
                    const float cc = cosb[spos * HALF + fi];
                    const float ss = sinb[spos * HALF + fi];
                    const float r0 = v0 * cc - v1 * ss;
                    const float r1 = v0 * ss + v1 * cc;
                    v0 = r0; v1 = r1;
                }
                float2 st; st.x = v0; st.y = v1;
                *(float2*)(crow + n) = st;
            }
        }
    }
}

// ---------------------------------------------------------------------------
// Tensor-core flash attention (tf32 mma.sync) — unchanged from R7.
// CTA = 128 queries of one (b,h); 8 warps x 16 rows; KV tiles of 64.
// ---------------------------------------------------------------------------
#define KST 68
#define VST 72
#define PST 68
#define ATTN_SMEM ((64 * KST + 64 * VST + 128 * PST) * 4)   // 70656 bytes

__global__ void __launch_bounds__(256, 1)
attn_mma_kernel()
{
    extern __shared__ float smf[];
    float* kt = smf;
    float* vt = kt + 64 * KST;
    float* pt = vt + 64 * VST;

    const int b  = blockIdx.z;
    const int h  = blockIdx.y;
    const int q0 = blockIdx.x * 128;
    const int tid = threadIdx.x;
    const int w   = tid >> 5;
    const int lid = tid & 31;
    const int lm = lid >> 2;
    const int lk = lid & 3;
    const int ln = lk * 2;

    const float* qg = g_q + ((size_t)(b * SEQ + q0) * DMODEL + h * HDIM);
    #pragma unroll
    for (int i = 0; i < 8; i++) {
        int idx = tid + i * 256;
        int row = idx >> 4;
        int c4  = (idx & 15) * 4;
        float4 v = *(const float4*)(qg + (size_t)row * DMODEL + c4);
        v.x = tf32r(v.x * 0.125f); v.y = tf32r(v.y * 0.125f);
        v.z = tf32r(v.z * 0.125f); v.w = tf32r(v.w * 0.125f);
        *(float4*)(pt + row * PST + c4) = v;
    }
    __syncthreads();

    uint32_t aq[8][4];
    {
        const float* qs = pt + (w * 16 + lm) * PST + lk;
        #pragma unroll
        for (int ks = 0; ks < 8; ks++) {
            aq[ks][0] = __float_as_uint(qs[ks * 8]);
            aq[ks][1] = __float_as_uint(qs[8 * PST + ks * 8]);
            aq[ks][2] = __float_as_uint(qs[ks * 8 + 4]);
            aq[ks][3] = __float_as_uint(qs[8 * PST + ks * 8 + 4]);
        }
    }

    float m0 = -1e30f, m1 = -1e30f, l0 = 0.f, l1 = 0.f;
    float oacc[8][4];
    #pragma unroll
    for (int nt = 0; nt < 8; nt++)
        #pragma unroll
        for (int r = 0; r < 4; r++) oacc[nt][r] = 0.f;

    const float* kg = g_k + ((size_t)(b * SEQ) * DMODEL + h * HDIM);
    const float* vg = g_v + ((size_t)(b * SEQ) * DMODEL + h * HDIM);

    const int ntiles = q0 / 64 + 2;
    for (int t = 0; t < ntiles; t++) {
        const int kv0 = t * 64;
        #pragma unroll
        for (int i = 0; i < 4; i++) {
            int idx = tid + i * 256;
            int row = idx >> 4;
            int c4  = (idx & 15) * 4;
            float4 kk = *(const float4*)(kg + (size_t)(kv0 + row) * DMODEL + c4);
            kk.x = tf32r(kk.x); kk.y = tf32r(kk.y);
            kk.z = tf32r(kk.z); kk.w = tf32r(kk.w);
            *(float4*)(kt + row * KST + c4) = kk;
            float4 vv = *(const float4*)(vg + (size_t)(kv0 + row) * DMODEL + c4);
            vv.x = tf32r(vv.x); vv.y = tf32r(vv.y);
            vv.z = tf32r(vv.z); vv.w = tf32r(vv.w);
            *(float4*)(vt + row * VST + c4) = vv;
        }
        __syncthreads();

        const bool active = !(w < 4 && t == ntiles - 1);
        if (active) {
            float sacc[8][4];
            #pragma unroll
            for (int nt = 0; nt < 8; nt++)
                #pragma unroll
                for (int r = 0; r < 4; r++) sacc[nt][r] = 0.f;

            #pragma unroll
            for (int ks = 0; ks < 8; ks++) {
                #pragma unroll
                for (int nt = 0; nt < 8; nt++) {
                    uint32_t b0 = __float_as_uint(kt[(nt * 8 + lm) * KST + ks * 8 + lk]);
                    uint32_t b1 = __float_as_uint(kt[(nt * 8 + lm) * KST + ks * 8 + lk + 4]);
                    mma_tf32(sacc[nt], aq[ks][0], aq[ks][1], aq[ks][2], aq[ks][3], b0, b1);
                }
            }

            if (t >= ntiles - 2) {
                const int rel0 = q0 + w * 16 + lm - kv0;
                const int rel1 = rel0 + 8;
                #pragma unroll
                for (int nt = 0; nt < 8; nt++) {
                    const int c0 = nt * 8 + ln;
                    if (c0     > rel0) sacc[nt][0] = -1e30f;
                    if (c0 + 1 > rel0) sacc[nt][1] = -1e30f;
                    if (c0     > rel1) sacc[nt][2] = -1e30f;
                    if (c0 + 1 > rel1) sacc[nt][3] = -1e30f;
                }
            }

            float rm0 = -1e30f, rm1 = -1e30f;
            #pragma unroll
            for (int nt = 0; nt < 8; nt++) {
                rm0 = fmaxf(rm0, fmaxf(sacc[nt][0], sacc[nt][1]));
                rm1 = fmaxf(rm1, fmaxf(sacc[nt][2], sacc[nt][3]));
            }
            rm0 = fmaxf(rm0, __shfl_xor_sync(0xffffffffu, rm0, 1));
            rm0 = fmaxf(rm0, __shfl_xor_sync(0xffffffffu, rm0, 2));
            rm1 = fmaxf(rm1, __shfl_xor_sync(0xffffffffu, rm1, 1));
            rm1 = fmaxf(rm1, __shfl_xor_sync(0xffffffffu, rm1, 2));

            const float mn0 = fmaxf(m0, rm0);
            const float mn1 = fmaxf(m1, rm1);
            const float sc0 = __expf(m0 - mn0);
            const float sc1 = __expf(m1 - mn1);
            m0 = mn0; m1 = mn1;
            l0 *= sc0; l1 *= sc1;
            #pragma unroll
            for (int nt = 0; nt < 8; nt++) {
                oacc[nt][0] *= sc0; oacc[nt][1] *= sc0;
                oacc[nt][2] *= sc1; oacc[nt][3] *= sc1;
            }

            float* pw = pt + (w * 16 + lm) * PST;
            #pragma unroll
            for (int nt = 0; nt < 8; nt++) {
                const float p0 = __expf(sacc[nt][0] - m0);
                const float p1 = __expf(sacc[nt][1] - m0);
                const float p2 = __expf(sacc[nt][2] - m1);
                const float p3 = __expf(sacc[nt][3] - m1);
                l0 += p0 + p1;
                l1 += p2 + p3;
                *(float2*)(pw + nt * 8 + ln)           = make_float2(p0, p1);
                *(float2*)(pw + 8 * PST + nt * 8 + ln) = make_float2(p2, p3);
            }
            __syncwarp();

            const float* pa = pt + (w * 16 + lm) * PST + lk;
            #pragma unroll
            for (int ks = 0; ks < 8; ks++) {
                const uint32_t a0 = __float_as_uint(pa[ks * 8]);
                const uint32_t a1 = __float_as_uint(pa[8 * PST + ks * 8]);
                const uint32_t a2 = __float_as_uint(pa[ks * 8 + 4]);
                const uint32_t a3 = __float_as_uint(pa[8 * PST + ks * 8 + 4]);
                #pragma unroll
                for (int nt = 0; nt < 8; nt++) {
                    uint32_t b0 = __float_as_uint(vt[(ks * 8 + lk) * VST + nt * 8 + lm]);
                    uint32_t b1 = __float_as_uint(vt[(ks * 8 + lk + 4) * VST + nt * 8 + lm]);
                    mma_tf32(oacc[nt], a0, a1, a2, a3, b0, b1);
                }
            }
        }
        __syncthreads();
    }

    l0 += __shfl_xor_sync(0xffffffffu, l0, 1);
    l0 += __shfl_xor_sync(0xffffffffu, l0, 2);
    l1 += __shfl_xor_sync(0xffffffffu, l1, 1);
    l1 += __shfl_xor_sync(0xffffffffu, l1, 2);
    const float inv0 = 1.f / l0;
    const float inv1 = 1.f / l1;

    float* og = g_attn + ((size_t)(b * SEQ + q0 + w * 16 + lm) * DMODEL + h * HDIM);
    #pragma unroll
    for (int nt = 0; nt < 8; nt++) {
        *(float2*)(og + nt * 8 + ln) =
            make_float2(oacc[nt][0] * inv0, oacc[nt][1] * inv0);
        *(float2*)(og + 8 * DMODEL + nt * 8 + ln) =
            make_float2(oacc[nt][2] * inv1, oacc[nt][3] * inv1);
    }
}

// ---------------------------------------------------------------------------
// Launch
// ---------------------------------------------------------------------------
extern "C" void kernel_launch(void* const* d_in, const int* in_sizes, int n_in,
                              void* d_out, int out_size)
{
    (void)in_sizes; (void)n_in; (void)out_size;
    const float* x       = (const float*)d_in[0];
    const float* pos_cos = (const float*)d_in[1];
    const float* pos_sin = (const float*)d_in[2];
    const float* wq_w    = (const float*)d_in[3];
    const float* wq_b    = (const float*)d_in[4];
    const float* wk_w    = (const float*)d_in[5];
    const float* wk_b    = (const float*)d_in[6];
    const float* wv_w    = (const float*)d_in[7];
    const float* wv_b    = (const float*)d_in[8];
    const float* wo_w    = (const float*)d_in[9];
    const float* wo_b    = (const float*)d_in[10];
    float* out = (float*)d_out;

    float *qp, *kp, *vp, *ap;
    cudaGetSymbolAddress((void**)&qp, g_q);
    cudaGetSymbolAddress((void**)&kp, g_k);
    cudaGetSymbolAddress((void**)&vp, g_v);
    cudaGetSymbolAddress((void**)&ap, g_attn);

    cudaFuncSetAttribute(gemm_tf32_kernel,
                         cudaFuncAttributeMaxDynamicSharedMemorySize, SMEM_DYN);
    cudaFuncSetAttribute(attn_mma_kernel,
                         cudaFuncAttributeMaxDynamicSharedMemorySize, ATTN_SMEM);

    dim3 gg(DMODEL / BN, MROWS / BM);   // (8, 32)
    gemm_tf32_kernel<<<gg, 512, SMEM_DYN>>>(x, wq_w, wq_b, qp, pos_cos, pos_sin, 1);
    gemm_tf32_kernel<<<gg, 512, SMEM_DYN>>>(x, wk_w, wk_b, kp, pos_cos, pos_sin, 1);
    gemm_tf32_kernel<<<gg, 512, SMEM_DYN>>>(x, wv_w, wv_b, vp, pos_cos, pos_sin, 0);

    dim3 ga(SEQ / 128, NHEAD, BATCH);   // (16, 16, 2)
    attn_mma_kernel<<<ga, 256, ATTN_SMEM>>>();

    gemm_tf32_kernel<<<gg, 512, SMEM_DYN>>>(ap, wo_w, wo_b, out, pos_cos, pos_sin, 0);
}